// round 11
// baseline (speedup 1.0000x reference)
#include <cuda_runtime.h>
#include <cstdint>

// RoiPoolingConv v11: quad-dedup gather.
//   CTA = one 2x2 output quad (128 threads, thread = 16B channel chunk).
//   Unique corner rows/cols of the quad computed in warp-uniform ALU
//   (monotone merge, <=4 each); the 4x4 (row,col) slots are predicated
//   LDG.128 + fma2 — invalid slots issue NO memory request. Separable
//   accumulation; 4 streaming STG.128 per thread.
//   Cuts read lines/warp 64 -> ~51 at identical store traffic.

__device__ __forceinline__ uint64_t pack2(float f) {
    uint64_t r; unsigned u = __float_as_uint(f);
    asm("mov.b64 %0, {%1,%1};" : "=l"(r) : "r"(u));
    return r;
}
__device__ __forceinline__ uint64_t fma2(uint64_t a, uint64_t b, uint64_t c) {
    uint64_t r;
    asm("fma.rn.f32x2 %0, %1, %2, %3;" : "=l"(r) : "l"(a), "l"(b), "l"(c));
    return r;
}
__device__ __forceinline__ void stcs2(char* p, uint64_t lo, uint64_t hi) {
    asm volatile("st.global.cs.v2.u64 [%0], {%1,%2};"
                 :: "l"(p), "l"(lo), "l"(hi) : "memory");
}

// Predicated slot: if valid, load 16B and accumulate into hA/hB with packed
// column weights. Predicated-off load issues no L1 wavefront.
__device__ __forceinline__ void slot(int valid, const char* ptr,
                                     uint64_t cwA, uint64_t cwB,
                                     uint64_t& hAlo, uint64_t& hAhi,
                                     uint64_t& hBlo, uint64_t& hBhi)
{
    asm("{\n\t"
        ".reg .pred p; .reg .b64 vlo; .reg .b64 vhi;\n\t"
        "setp.ne.s32 p, %4, 0;\n\t"
        "@p ld.global.nc.v2.u64 {vlo, vhi}, [%5];\n\t"
        "@p fma.rn.f32x2 %0, vlo, %6, %0;\n\t"
        "@p fma.rn.f32x2 %1, vhi, %6, %1;\n\t"
        "@p fma.rn.f32x2 %2, vlo, %7, %2;\n\t"
        "@p fma.rn.f32x2 %3, vhi, %7, %3;\n\t"
        "}"
        : "+l"(hAlo), "+l"(hAhi), "+l"(hBlo), "+l"(hBhi)
        : "r"(valid), "l"(ptr), "l"(cwA), "l"(cwB));
}

// Corner dedup for an adjacent pixel pair (ia, ib) on one axis.
// Emits <=4 entries: index c[k], weight for output A / output B, validity.
// fp32 sequence matches the reference exactly up to the floor.
__device__ __forceinline__ void axis_pair(int ia, int ib, int size, int origin,
                                          float poolf,
                                          int* c, float* wA, float* wB, int* v)
{
    float sf    = (float)size;
    float scale = __fdiv_rn(sf, poolf);

    float sa = __fsub_rn(__fmul_rn((float)ia + 0.5f, scale), 0.5f);
    sa = fminf(fmaxf(sa, 0.0f), sf - 1.0f);
    int a0 = (int)sa; int a1 = min(a0 + 1, size - 1);
    float fa = sa - (float)a0;

    float sb = __fsub_rn(__fmul_rn((float)ib + 0.5f, scale), 0.5f);
    sb = fminf(fmaxf(sb, 0.0f), sf - 1.0f);
    int b0 = (int)sb; int b1 = min(b0 + 1, size - 1);
    float fb = sb - (float)b0;

    float ga = 1.0f - fa, gb = 1.0f - fb;

    // monotone: a0<=b0, a1<=b1, a0<=a1, b0<=b1
    bool p  = (b0 == a0);
    bool q1 = (b0 == a1);
    bool r2 = (b1 == a1);
    bool v1 = (a1 > a0);     // if false, fa == 0 (degenerate pixel a)
    bool s2 = (b1 > a1);

    c[0] = origin + a0; wA[0] = ga;   wB[0] = p ? gb : 0.0f;  v[0] = 1;
    c[1] = origin + a1; wA[1] = fa;
    wB[1] = v1 ? ((q1 ? gb : 0.0f) + (r2 ? fb : 0.0f)) : 0.0f;
    v[1] = v1 ? 1 : 0;
    c[2] = origin + b0; wA[2] = 0.0f; wB[2] = gb;  v[2] = (!p && !q1) ? 1 : 0;
    c[3] = origin + b1; wA[3] = 0.0f; wB[3] = fb;  v[3] = s2 ? 1 : 0;
}

__global__ void __launch_bounds__(128)
roi_quad_kernel(const float* __restrict__ img,
                const int*   __restrict__ rois,
                float*       __restrict__ out,
                int pool, int qpool, unsigned magicq, int W)
{
    const int r  = blockIdx.y;
    const int q  = blockIdx.x;
    const int qy = (int)(((unsigned long long)q * magicq) >> 22);
    const int qx = q - qy * qpool;

    const int pxa = 2 * qx, pxb = min(2 * qx + 1, pool - 1);
    const int pya = 2 * qy, pyb = min(2 * qy + 1, pool - 1);

    const int4 roi = __ldg(((const int4*)rois) + r);
    const float poolf = (float)pool;

    int   rc[4]; float rwA[4], rwB[4]; int rv[4];
    axis_pair(pya, pyb, roi.w, roi.y, poolf, rc, rwA, rwB, rv);
    int   cc[4]; float cwAf[4], cwBf[4]; int cv[4];
    axis_pair(pxa, pxb, roi.z, roi.x, poolf, cc, cwAf, cwBf, cv);

    uint64_t cwA[4], cwB[4];
    #pragma unroll
    for (int j = 0; j < 4; ++j) {
        cwA[j] = pack2(cwAf[j]);
        cwB[j] = pack2(cwBf[j]);
    }

    // accumulators: out(rowA/B, colA/B), each 16B as 2x u64
    uint64_t aAAlo = 0, aAAhi = 0, aABlo = 0, aABhi = 0;
    uint64_t aBAlo = 0, aBAhi = 0, aBBlo = 0, aBBhi = 0;

    // chunk base: C4 = 128 chunks of 16B -> pixel stride 2048B
    const char* base = (const char*)img + ((size_t)threadIdx.x << 4);

    #pragma unroll
    for (int i = 0; i < 4; ++i) {
        uint64_t hAlo = 0, hAhi = 0, hBlo = 0, hBhi = 0;
        const char* rowp = base + (size_t)(rc[i] * W) * 2048;
        #pragma unroll
        for (int j = 0; j < 4; ++j) {
            slot(rv[i] & cv[j], rowp + (size_t)cc[j] * 2048,
                 cwA[j], cwB[j], hAlo, hAhi, hBlo, hBhi);
        }
        const uint64_t rA = pack2(rwA[i]);
        const uint64_t rB = pack2(rwB[i]);
        aAAlo = fma2(hAlo, rA, aAAlo); aAAhi = fma2(hAhi, rA, aAAhi);
        aABlo = fma2(hBlo, rA, aABlo); aABhi = fma2(hBhi, rA, aABhi);
        aBAlo = fma2(hAlo, rB, aBAlo); aBAhi = fma2(hAhi, rB, aBAhi);
        aBBlo = fma2(hBlo, rB, aBBlo); aBBhi = fma2(hBhi, rB, aBBhi);
    }

    char* outp = (char*)out + ((size_t)threadIdx.x << 4);
    const size_t rowbase = (size_t)(r * pool) * pool;
    stcs2(outp + (rowbase + (size_t)pya * pool + pxa) * 2048, aAAlo, aAAhi);
    stcs2(outp + (rowbase + (size_t)pya * pool + pxb) * 2048, aABlo, aABhi);
    stcs2(outp + (rowbase + (size_t)pyb * pool + pxa) * 2048, aBAlo, aBAhi);
    stcs2(outp + (rowbase + (size_t)pyb * pool + pxb) * 2048, aBBlo, aBBhi);
}

extern "C" void kernel_launch(void* const* d_in, const int* in_sizes, int n_in,
                              void* d_out, int out_size)
{
    const float* img  = (const float*)d_in[0];
    const int*   rois = (const int*)d_in[1];
    float*       out  = (float*)d_out;

    const int H = 128, W = 128;
    const int C        = in_sizes[0] / (H * W);      // 512
    const int num_rois = in_sizes[1] / 4;            // 256

    const int pp = out_size / (num_rois * C);        // pool^2 = 196
    int pool = 1;
    while (pool * pool < pp) pool++;                 // 14

    const int qpool = (pool + 1) / 2;                // 7
    unsigned magicq = (unsigned)((4194304u + qpool - 1) / qpool);

    dim3 grid(qpool * qpool, num_rois);              // (49, 256)
    roi_quad_kernel<<<grid, 128>>>(img, rois, out, pool, qpool, magicq, W);
}

// round 12
// speedup vs baseline: 1.3490x; 1.3490x over previous
#include <cuda_runtime.h>
#include <cstdint>

// RoiPoolingConv v12: pixel-pair warp + warp-uniform 3-case x-dedup.
//   Warp = 2 x-adjacent output pixels (shared y rows). Monotone x corners
//   give exactly 3 cases, dispatched by a warp-uniform branch:
//     xB0==xA0 -> B corners == A corners (4 loads/chunk for both pixels)
//     xB0==xA1 -> share one column       (6 loads/chunk)
//     else     -> disjoint               (8 loads/chunk, two R8 bodies)
//   fma2 packed datapath + streaming STG.128 kept from R8.

__device__ __forceinline__ uint64_t pack2(float f) {
    uint64_t r; unsigned u = __float_as_uint(f);
    asm("mov.b64 %0, {%1,%1};" : "=l"(r) : "r"(u));
    return r;
}
__device__ __forceinline__ uint64_t fma2(uint64_t a, uint64_t b, uint64_t c) {
    uint64_t r;
    asm("fma.rn.f32x2 %0, %1, %2, %3;" : "=l"(r) : "l"(a), "l"(b), "l"(c));
    return r;
}
__device__ __forceinline__ uint64_t mul2(uint64_t a, uint64_t b) {
    uint64_t r;
    asm("mul.rn.f32x2 %0, %1, %2;" : "=l"(r) : "l"(a), "l"(b));
    return r;
}

struct V2 { uint64_t lo, hi; };

__device__ __forceinline__ V2 ldg2(const char* p) {
    V2 v;
    asm("ld.global.nc.v2.u64 {%0,%1}, [%2];"
        : "=l"(v.lo), "=l"(v.hi) : "l"(p));
    return v;
}
__device__ __forceinline__ void stcs2(char* p, V2 v) {
    asm volatile("st.global.cs.v2.u64 [%0], {%1,%2};"
                 :: "l"(p), "l"(v.lo), "l"(v.hi) : "memory");
}

__device__ __forceinline__ V2 blendv(V2 a, V2 b, V2 d, V2 e,
                                     uint64_t W00, uint64_t W01,
                                     uint64_t W10, uint64_t W11)
{
    V2 r;
    r.lo = fma2(a.lo, W00, fma2(b.lo, W01, fma2(d.lo, W10, mul2(e.lo, W11))));
    r.hi = fma2(a.hi, W00, fma2(b.hi, W01, fma2(d.hi, W10, mul2(e.hi, W11))));
    return r;
}

// Reference-exact axis corners: scale = size/pool; s = (i+0.5)*scale - 0.5;
// clip; floor; frac. Returns global indices.
__device__ __forceinline__ void axis1(int i, int size, int origin, float poolf,
                                      int& g0, int& g1, float& f)
{
    float sf    = (float)size;
    float scale = __fdiv_rn(sf, poolf);
    float s     = __fsub_rn(__fmul_rn((float)i + 0.5f, scale), 0.5f);
    s = fminf(fmaxf(s, 0.0f), sf - 1.0f);
    int i0 = (int)s;
    int i1 = min(i0 + 1, size - 1);
    f  = s - (float)i0;
    g0 = origin + i0;
    g1 = origin + i1;
}

__global__ void __launch_bounds__(128, 10)
roi_pair_kernel(const float* __restrict__ img,
                const int*   __restrict__ rois,
                float*       __restrict__ out,
                int pool, int ppr, int npairs, unsigned magic, int W)
{
    const int r  = blockIdx.y;
    const int pq = blockIdx.x * 4 + (threadIdx.x >> 5);   // pair index
    if (pq >= npairs) return;
    const int lane = threadIdx.x & 31;

    const int4 roi = __ldg(((const int4*)rois) + r);

    // pq < pool*ppr <= 4096: exact magic division by ppr via 2^22
    const int py  = (int)(((unsigned long long)pq * magic) >> 22);
    const int qx  = pq - py * ppr;
    const int pxA = 2 * qx;
    const int pxB = min(pxA + 1, pool - 1);

    const float poolf = (float)pool;

    int y0, y1; float fy;
    axis1(py,  roi.w, roi.y, poolf, y0, y1, fy);
    int xA0, xA1; float fxA;
    axis1(pxA, roi.z, roi.x, poolf, xA0, xA1, fxA);
    int xB0, xB1; float fxB;
    axis1(pxB, roi.z, roi.x, poolf, xB0, xB1, fxB);

    const float gy = 1.0f - fy;
    const float gA = 1.0f - fxA, gB = 1.0f - fxB;
    const uint64_t WA00 = pack2(gA * gy), WA01 = pack2(fxA * gy);
    const uint64_t WA10 = pack2(gA * fy), WA11 = pack2(fxA * fy);
    const uint64_t WB00 = pack2(gB * gy), WB01 = pack2(fxB * gy);
    const uint64_t WB10 = pack2(gB * fy), WB11 = pack2(fxB * fy);

    const char* base = (const char*)img + ((size_t)lane << 4);
    const char* rt = base + (size_t)(y0 * W) * 2048;   // top row
    const char* rb = base + (size_t)(y1 * W) * 2048;   // bottom row
    const char* pA0t = rt + (size_t)xA0 * 2048;
    const char* pA1t = rt + (size_t)xA1 * 2048;
    const char* pA0b = rb + (size_t)xA0 * 2048;
    const char* pA1b = rb + (size_t)xA1 * 2048;

    const size_t obase = (size_t)((r * pool + py) * pool);
    char* oA = (char*)out + (obase + pxA) * 2048 + ((size_t)lane << 4);
    char* oB = (char*)out + (obase + pxB) * 2048 + ((size_t)lane << 4);

    if (xB0 == xA0) {
        // B corners identical to A's (xB1 == xA1 provably)
        #pragma unroll
        for (int k = 0; k < 4; ++k) {
            const int o = k * 512;
            V2 a = ldg2(pA0t + o), b = ldg2(pA1t + o);
            V2 d = ldg2(pA0b + o), e = ldg2(pA1b + o);
            stcs2(oA + o, blendv(a, b, d, e, WA00, WA01, WA10, WA11));
            stcs2(oB + o, blendv(a, b, d, e, WB00, WB01, WB10, WB11));
        }
    } else if (xB0 == xA1) {
        // shared middle column; only xB1 is new
        const char* pNt = rt + (size_t)xB1 * 2048;
        const char* pNb = rb + (size_t)xB1 * 2048;
        #pragma unroll
        for (int k = 0; k < 4; ++k) {
            const int o = k * 512;
            V2 a  = ldg2(pA0t + o), b  = ldg2(pA1t + o);
            V2 d  = ldg2(pA0b + o), e  = ldg2(pA1b + o);
            V2 n0 = ldg2(pNt  + o), n1 = ldg2(pNb  + o);
            stcs2(oA + o, blendv(a, b, d, e,  WA00, WA01, WA10, WA11));
            stcs2(oB + o, blendv(b, n0, e, n1, WB00, WB01, WB10, WB11));
        }
    } else {
        // disjoint columns: two full bodies
        const char* pB0t = rt + (size_t)xB0 * 2048;
        const char* pB1t = rt + (size_t)xB1 * 2048;
        const char* pB0b = rb + (size_t)xB0 * 2048;
        const char* pB1b = rb + (size_t)xB1 * 2048;
        #pragma unroll
        for (int k = 0; k < 4; ++k) {
            const int o = k * 512;
            V2 a  = ldg2(pA0t + o), b  = ldg2(pA1t + o);
            V2 d  = ldg2(pA0b + o), e  = ldg2(pA1b + o);
            V2 a2 = ldg2(pB0t + o), b2 = ldg2(pB1t + o);
            V2 d2 = ldg2(pB0b + o), e2 = ldg2(pB1b + o);
            stcs2(oA + o, blendv(a,  b,  d,  e,  WA00, WA01, WA10, WA11));
            stcs2(oB + o, blendv(a2, b2, d2, e2, WB00, WB01, WB10, WB11));
        }
    }
}

extern "C" void kernel_launch(void* const* d_in, const int* in_sizes, int n_in,
                              void* d_out, int out_size)
{
    const float* img  = (const float*)d_in[0];
    const int*   rois = (const int*)d_in[1];
    float*       out  = (float*)d_out;

    const int H = 128, W = 128;
    const int C        = in_sizes[0] / (H * W);      // 512
    const int num_rois = in_sizes[1] / 4;            // 256

    const int pp = out_size / (num_rois * C);        // pool^2 = 196
    int pool = 1;
    while (pool * pool < pp) pool++;                 // 14

    const int ppr    = (pool + 1) / 2;               // pairs per row = 7
    const int npairs = pool * ppr;                   // 98

    // magic for exact n/ppr, n < ~800K: m = ceil(2^22 / ppr)
    unsigned magic = (unsigned)((4194304u + ppr - 1) / ppr);

    dim3 grid((npairs + 3) / 4, num_rois);           // (25, 256)
    roi_pair_kernel<<<grid, 128>>>(img, rois, out, pool, ppr, npairs, magic, W);
}